// round 1
// baseline (speedup 1.0000x reference)
#include <cuda_runtime.h>

// RaySamples: volume rendering weights.
//   dd      = deltas * densities                       [N, K]
//   alphas  = 1 - exp(-dd)
//   acc     = exclusive cumsum of dd along K
//   T       = exp(-acc)
//   weights = alphas * T
// Outputs concatenated: d_out[0 : N*K] = weights, d_out[N*K : 2*N*K] = T.
//
// N = 65536 rays, K = 128 samples. One warp per ray; each lane owns a
// float4 (4 consecutive samples). Exclusive scan = in-lane prefix +
// warp shuffle scan of per-lane sums. Fully coalesced float4 LD/ST.

static constexpr int N_RAYS = 65536;
static constexpr int K_SAMPLES = 128;  // 32 float4 per ray == 1 float4 per lane

__global__ void __launch_bounds__(256) ray_samples_kernel(
    const float4* __restrict__ dens,
    const float4* __restrict__ delt,
    float4* __restrict__ w_out,
    float4* __restrict__ t_out)
{
    const int gtid = blockIdx.x * blockDim.x + threadIdx.x;
    const int lane = threadIdx.x & 31;
    // warp w handles ray w; lane l handles samples [4l, 4l+4)
    // global float4 index = warp_id * 32 + lane = gtid (since 32 lanes cover 32 float4)
    const int idx = gtid;

    const float4 d  = dens[idx];
    const float4 dl = delt[idx];

    const float dd0 = d.x * dl.x;
    const float dd1 = d.y * dl.y;
    const float dd2 = d.z * dl.z;
    const float dd3 = d.w * dl.w;

    const float local_sum = dd0 + dd1 + dd2 + dd3;

    // Inclusive warp scan of per-lane sums
    float scan = local_sum;
    #pragma unroll
    for (int off = 1; off < 32; off <<= 1) {
        float v = __shfl_up_sync(0xffffffffu, scan, off);
        if (lane >= off) scan += v;
    }
    const float excl = scan - local_sum;  // exclusive offset for this lane

    // Exclusive accumulated optical depth for each of the 4 samples
    const float a0 = excl;
    const float a1 = a0 + dd0;
    const float a2 = a1 + dd1;
    const float a3 = a2 + dd2;

    const float t0 = __expf(-a0);
    const float t1 = __expf(-a1);
    const float t2 = __expf(-a2);
    const float t3 = __expf(-a3);

    float4 T = make_float4(t0, t1, t2, t3);
    float4 W = make_float4((1.0f - __expf(-dd0)) * t0,
                           (1.0f - __expf(-dd1)) * t1,
                           (1.0f - __expf(-dd2)) * t2,
                           (1.0f - __expf(-dd3)) * t3);

    w_out[idx] = W;
    t_out[idx] = T;
}

extern "C" void kernel_launch(void* const* d_in, const int* in_sizes, int n_in,
                              void* d_out, int out_size)
{
    const float4* dens = (const float4*)d_in[0];  // densities [N, K, 1] fp32
    const float4* delt = (const float4*)d_in[1];  // deltas    [N, K, 1] fp32
    float* out = (float*)d_out;

    const int total_elems = N_RAYS * K_SAMPLES;      // per-output element count
    float4* w_out = (float4*)out;                    // first half: weights
    float4* t_out = (float4*)(out + total_elems);    // second half: transmittance

    const int total_f4 = total_elems / 4;            // 2,097,152 float4
    const int threads = 256;
    const int blocks = total_f4 / threads;           // 8192
    ray_samples_kernel<<<blocks, threads>>>(dens, delt, w_out, t_out);
}

// round 2
// speedup vs baseline: 1.1099x; 1.1099x over previous
#include <cuda_runtime.h>

// RaySamples volume rendering, round 2.
// 8 samples per thread (2 float4 per input), 2 rays per warp.
// Two independent width-16 shuffle scans (lo/hi half of each ray) ->
// shorter critical path per sample, MLP=4 front-batched loads.
// MUFU reduction: t_{i+1} = t_i * e_i reuses e_i = exp(-dd_i) from alpha.
//
// Output: d_out[0:N*K] = weights, d_out[N*K:2N*K] = transmittance.

static constexpr int N_RAYS = 65536;
static constexpr int K_SAMPLES = 128;   // 32 float4 per ray

__global__ void __launch_bounds__(256) ray_samples_kernel(
    const float4* __restrict__ dens,
    const float4* __restrict__ delt,
    float4* __restrict__ w_out,
    float4* __restrict__ t_out)
{
    const int lane = threadIdx.x & 31;
    const int warp_global = (blockIdx.x * blockDim.x + threadIdx.x) >> 5;
    const int sub = lane & 15;               // position within half-warp
    const int ray = warp_global * 2 + (lane >> 4);

    const int base_f4 = ray * (K_SAMPLES / 4);   // 32 float4 per ray
    const int i_lo = base_f4 + sub;              // samples [4*sub, 4*sub+4)
    const int i_hi = base_f4 + 16 + sub;         // samples [64+4*sub, ...)

    // Front-batched loads: MLP = 4
    const float4 d_lo  = __ldcs(&dens[i_lo]);
    const float4 d_hi  = __ldcs(&dens[i_hi]);
    const float4 dl_lo = __ldcs(&delt[i_lo]);
    const float4 dl_hi = __ldcs(&delt[i_hi]);

    const float dd0 = d_lo.x * dl_lo.x;
    const float dd1 = d_lo.y * dl_lo.y;
    const float dd2 = d_lo.z * dl_lo.z;
    const float dd3 = d_lo.w * dl_lo.w;
    const float dd4 = d_hi.x * dl_hi.x;
    const float dd5 = d_hi.y * dl_hi.y;
    const float dd6 = d_hi.z * dl_hi.z;
    const float dd7 = d_hi.w * dl_hi.w;

    const float s_lo = (dd0 + dd1) + (dd2 + dd3);
    const float s_hi = (dd4 + dd5) + (dd6 + dd7);

    // Two independent width-16 inclusive scans (segments = half-warps).
    float scan_lo = s_lo;
    float scan_hi = s_hi;
    #pragma unroll
    for (int off = 1; off < 16; off <<= 1) {
        float vl = __shfl_up_sync(0xffffffffu, scan_lo, off);
        float vh = __shfl_up_sync(0xffffffffu, scan_hi, off);
        if (sub >= off) { scan_lo += vl; scan_hi += vh; }
    }
    const float excl_lo_part = scan_lo - s_lo;
    const float excl_hi_part = scan_hi - s_hi;

    // Total of the lo half (inclusive scan at sub==15 of this half-warp)
    const float total_lo = __shfl_sync(0xffffffffu, scan_lo, (lane & 16) | 15);

    const float excl_lo = excl_lo_part;
    const float excl_hi = total_lo + excl_hi_part;

    // Per-sample exp(-dd): needed for alphas AND reused for the T chain.
    const float e0 = __expf(-dd0);
    const float e1 = __expf(-dd1);
    const float e2 = __expf(-dd2);
    const float e3 = __expf(-dd3);
    const float e4 = __expf(-dd4);
    const float e5 = __expf(-dd5);
    const float e6 = __expf(-dd6);
    const float e7 = __expf(-dd7);

    // Transmittance: T_0 = exp(-excl), T_{i+1} = T_i * e_i
    const float t0 = __expf(-excl_lo);
    const float t1 = t0 * e0;
    const float t2 = t1 * e1;
    const float t3 = t2 * e2;
    const float t4 = __expf(-excl_hi);
    const float t5 = t4 * e4;
    const float t6 = t5 * e5;
    const float t7 = t6 * e6;

    const float4 T_lo = make_float4(t0, t1, t2, t3);
    const float4 T_hi = make_float4(t4, t5, t6, t7);
    const float4 W_lo = make_float4((1.0f - e0) * t0,
                                    (1.0f - e1) * t1,
                                    (1.0f - e2) * t2,
                                    (1.0f - e3) * t3);
    const float4 W_hi = make_float4((1.0f - e4) * t4,
                                    (1.0f - e5) * t5,
                                    (1.0f - e6) * t6,
                                    (1.0f - e7) * t7);

    __stcs(&w_out[i_lo], W_lo);
    __stcs(&w_out[i_hi], W_hi);
    __stcs(&t_out[i_lo], T_lo);
    __stcs(&t_out[i_hi], T_hi);
}

extern "C" void kernel_launch(void* const* d_in, const int* in_sizes, int n_in,
                              void* d_out, int out_size)
{
    const float4* dens = (const float4*)d_in[0];
    const float4* delt = (const float4*)d_in[1];
    float* out = (float*)d_out;

    const int total_elems = N_RAYS * K_SAMPLES;
    float4* w_out = (float4*)out;
    float4* t_out = (float4*)(out + total_elems);

    // 8 samples per thread -> N*K/8 threads
    const int threads = 256;
    const int total_threads = total_elems / 8;   // 1,048,576
    const int blocks = total_threads / threads;  // 4096
    ray_samples_kernel<<<blocks, threads>>>(dens, delt, w_out, t_out);
}